// round 14
// baseline (speedup 1.0000x reference)
#include <cuda_runtime.h>
#include <stdint.h>

#define BATCH 32
#define NBOX 24564
#define NBPAD 24576          // padded to 6144 uint4 per image
#define ROW 93
#define NUM_PRED 10
#define DB 64                // boxes per CTA / threads per CTA
#define NCHUNK 384           // ceil(NBOX / DB)
#define NBIN 1024
#define CCAP 1024            // candidate capacity (reuses 24KB staging smem)
#define TARGET 128

typedef unsigned long long u64;

// Scratch (static device globals; zero-initialized at load).
// g_sb: score bits per box (0 = dead). key = ((u64)sb<<32) | (0xFFFFFFFF-idx).
__device__ unsigned g_sb [BATCH * NBPAD];
__device__ int      g_cls[BATCH * NBOX];
__device__ float4   g_box[BATCH * NBOX];
__device__ int      g_hist[BATCH * NBIN];
__device__ int      g_done[BATCH];

// Precise float exp: Cody-Waite + degree-6 FMA poly (~1 ulp), fast-math-proof.
__device__ __forceinline__ float exp_precise(float x) {
    x = fminf(fmaxf(x, -80.0f), 80.0f);
    float kf = rintf(x * 1.4426950408889634f);
    float r  = fmaf(-kf, 0.6931471824645996f, x);
    r        = fmaf(-kf, -1.904654323148236e-09f, r);
    float p  = 1.9875691500e-4f;
    p = fmaf(p, r, 1.3981999507e-3f);
    p = fmaf(p, r, 8.3334519073e-3f);
    p = fmaf(p, r, 4.1665795894e-2f);
    p = fmaf(p, r, 1.6666665459e-1f);
    p = fmaf(p, r, 5.0000000000e-1f);
    p = fmaf(p, r, 1.0f);
    p = fmaf(p, r, 1.0f);
    return p * __int_as_float(((int)kf + 127) << 23);
}

__device__ __forceinline__ void cp16(uint32_t dst_smem, const void* src) {
    asm volatile("cp.async.cg.shared.global [%0], [%1], 16;"
                 :: "r"(dst_smem), "l"(src));
}

__device__ __forceinline__ bool iou_gt(const float4& a, const float4& q) {
    float iw = fminf(a.z, q.z) - fmaxf(a.x, q.x); iw = fmaxf(iw, 0.0f);
    float ih = fminf(a.w, q.w) - fmaxf(a.y, q.y); ih = fmaxf(ih, 0.0f);
    float inter  = iw * ih;
    float area_a = (a.z - a.x) * (a.w - a.y);
    float area_q = (q.z - q.x) * (q.w - q.y);
    return inter / (area_a + area_q - inter + 1e-12f) > 0.35f;
}

#define AGG_STORE(sbv, IDX)                                              \
    {                                                                    \
        bool pass = ((sbv) >= fsb);                                      \
        unsigned m = __ballot_sync(FULL, pass);                          \
        if (m != 0u && pass) {                                           \
            int leader = __ffs(m) - 1;                                   \
            int wb;                                                      \
            if (lane == leader) wb = atomicAdd(&s_cnt, __popc(m));       \
            wb = __shfl_sync(m, wb, leader);                             \
            int slot = wb + __popc(m & ((1u << lane) - 1u));             \
            if (slot < CCAP) {                                           \
                int idx = (IDX);                                         \
                ckey[slot] = ((u64)(sbv) << 32) |                        \
                             (u64)(0xFFFFFFFFu - (unsigned)idx);         \
                cbox[slot] = g_box[b * NBOX + idx];                      \
            }                                                            \
        }                                                                \
    }

// Fused decode + last-CTA post. Grid (NCHUNK, BATCH), 64 threads.
// Decode: cp.async staging, per-thread argmax, score-bit histogram.
// The 384th CTA of each image (done-counter) runs the post phase inline:
// hist -> floor -> compact (>= floor) into smem -> warp-0 greedy NMS.
__global__ __launch_bounds__(DB) void fused_kernel(const float* __restrict__ y,
                                                   float* __restrict__ out) {
    __shared__ __align__(16) char sm[24576];  // staging rows | {cbox, ckey}
    __shared__ int h[NBIN];
    __shared__ int s_c[256];
    __shared__ int s_cnt;
    __shared__ unsigned s_fsb;
    __shared__ int s_last;

    const int b  = blockIdx.y;
    const int c0 = blockIdx.x * DB;
    const int nb = min(DB, NBOX - c0);
    const int nf4 = (nb * ROW) >> 2;
    const int t = threadIdx.x;
    const int lane = t & 31;
    const unsigned FULL = 0xffffffffu;
    float* s = (float*)sm;

    #pragma unroll
    for (int j = 0; j < NBIN / DB; j++) h[t + j * DB] = 0;
    {
        const float4* src = (const float4*)(y + ((size_t)b * NBOX + c0) * ROW);
        uint32_t sbase;
        asm("{ .reg .u64 tmp; cvta.to.shared.u64 tmp, %1; cvt.u32.u64 %0, tmp; }"
            : "=r"(sbase) : "l"(s));
        for (int i = t; i < nf4; i += DB) cp16(sbase + i * 16, src + i);
        asm volatile("cp.async.commit_group;" ::: "memory");
        asm volatile("cp.async.wait_group 0;" ::: "memory");
    }
    __syncthreads();

    if (t < nb) {
        const float* row = s + t * ROW;
        // argmax over 81 classes; '>' keeps first occurrence (jnp.argmax)
        float best = row[0]; int bi = 0;
        #pragma unroll
        for (int c = 1; c < 81; c++) {
            float v = row[c];
            if (v > best) { best = v; bi = c; }
        }
        const int box = c0 + t;
        if (bi != 0 && best >= 0.5f) {
            float o0 = row[81], o1 = row[82], o2 = row[83], o3 = row[84];
            float cxp = row[85], cyp = row[86], wp = row[87], hp = row[88];
            float va = row[89], vb = row[90], vc = row[91], vd = row[92];
            float cx = o0 * va * wp + cxp;
            float cy = o1 * vb * hp + cyp;
            float w  = exp_precise(o2 * vc) * wp;
            float hh = exp_precise(o3 * vd) * hp;
            float4 bx;
            bx.x = (cx - 0.5f * w)  * 512.0f;
            bx.y = (cy - 0.5f * hh) * 512.0f;
            bx.z = (cx + 0.5f * w)  * 512.0f;
            bx.w = (cy + 0.5f * hh) * 512.0f;
            unsigned sb = __float_as_uint(best);
            g_sb[b * NBPAD + box] = sb;
            g_cls[b * NBOX + box] = bi;
            g_box[b * NBOX + box] = bx;
            int bin = min(NBIN - 1, (int)((sb - 0x3F000000u) >> 13));
            atomicAdd(&h[bin], 1);
        } else {
            g_sb[b * NBPAD + box] = 0u;
        }
    }
    __syncthreads();
    #pragma unroll
    for (int j = 0; j < NBIN / DB; j++) {
        int i = t + j * DB;
        int c = h[i];
        if (c) atomicAdd(&g_hist[b * NBIN + i], c);
    }

    // ---- last-CTA handoff ----
    __threadfence();
    __syncthreads();
    if (t == 0) s_last = (atomicAdd(&g_done[b], 1) == NCHUNK - 1) ? 1 : 0;
    __syncthreads();
    if (!s_last) return;
    __threadfence();                         // acquire other CTAs' writes
    if (t == 0) { g_done[b] = 0; s_cnt = 0; }

    // ---- post phase (64 threads) ----
    #pragma unroll
    for (int j = 0; j < NBIN / DB; j++) {    // read + zero global hist
        int i = t + j * DB;
        h[i] = g_hist[b * NBIN + i];
        g_hist[b * NBIN + i] = 0;
    }
    if (t < NUM_PRED * 6) out[b * NUM_PRED * 6 + t] = 0.0f;
    __syncthreads();
    #pragma unroll
    for (int j = 0; j < 4; j++) {
        int i = t + j * DB;                  // 0..255
        s_c[i] = h[i*4] + h[i*4+1] + h[i*4+2] + h[i*4+3];
    }
    __syncthreads();

    // floor finder (warp 0)
    if (t < 32) {
        int W = 0;
        #pragma unroll
        for (int j = 0; j < 8; j++) W += s_c[lane * 8 + j];
        int suf = W;
        #pragma unroll
        for (int o = 1; o < 32; o <<= 1) {
            int v = __shfl_down_sync(FULL, suf, o);
            if (lane + o < 32) suf += v;
        }
        int sufnext = __shfl_down_sync(FULL, suf, 1);
        if (lane == 31) sufnext = 0;
        unsigned mask = __ballot_sync(FULL, suf >= TARGET);
        if (mask == 0u) {
            if (lane == 0) s_fsb = 0x3F000000u;        // admit all
        } else {
            int L = 31 - __clz(mask);
            if (lane == L) {
                int cum = sufnext;                     // < TARGET
                int T = 32 * L;
                #pragma unroll
                for (int jb = 31; jb >= 0; jb--) {
                    cum += h[32 * L + jb];
                    if (cum >= TARGET) { T = 32 * L + jb; break; }
                }
                s_fsb = 0x3F000000u + ((unsigned)T << 13);
            }
        }
    }
    __syncthreads();
    const unsigned fsb = s_fsb;

    // compact: 96 uint4 per thread, double-buffered groups of 8,
    // group-level any-ballot skip. Candidates into reused staging smem.
    float4* cbox = (float4*)sm;              // CCAP * 16 B
    u64*    ckey = (u64*)(sm + CCAP * 16);   // CCAP * 8 B
    {
        const uint4* sb4 = (const uint4*)(g_sb + b * NBPAD);
        uint4 v[8], w[8];
        #pragma unroll
        for (int j = 0; j < 8; j++) v[j] = sb4[t + j * DB];
        for (int g = 0; g < 12; g++) {
            if (g < 11) {
                #pragma unroll
                for (int j = 0; j < 8; j++)
                    w[j] = sb4[t + ((g + 1) * 8 + j) * DB];
            }
            unsigned mx = 0u;
            #pragma unroll
            for (int j = 0; j < 8; j++) {
                unsigned m1 = v[j].x > v[j].y ? v[j].x : v[j].y;
                unsigned m2 = v[j].z > v[j].w ? v[j].z : v[j].w;
                unsigned m3 = m1 > m2 ? m1 : m2;
                mx = mx > m3 ? mx : m3;
            }
            if (__ballot_sync(FULL, mx >= fsb) != 0u) {
                #pragma unroll
                for (int j = 0; j < 8; j++) {
                    int q4 = (t + (g * 8 + j) * DB) * 4;
                    AGG_STORE(v[j].x, q4 + 0)
                    AGG_STORE(v[j].y, q4 + 1)
                    AGG_STORE(v[j].z, q4 + 2)
                    AGG_STORE(v[j].w, q4 + 3)
                }
            }
            if (g < 11) {
                #pragma unroll
                for (int j = 0; j < 8; j++) v[j] = w[j];
            }
        }
    }
    __syncthreads();

    // warp 0: greedy NMS over the score-prefix set
    if (t >= 32) return;
    const bool fast = (s_cnt <= CCAP);
    const int M = fast ? s_cnt : 0;
    const int base = b * NBOX;
    float4 pick = make_float4(0.f, 0.f, 0.f, 0.f);   // lane i holds pick i
    int np = 0;

    while (np < NUM_PRED) {
        u64 lb = 0; int ls = -1;
        for (int i = lane; i < M; i += 32) {
            u64 k = ckey[i];
            if (k > lb) { lb = k; ls = i; }
        }
        u64 gb = lb;
        #pragma unroll
        for (int o = 16; o > 0; o >>= 1) {
            u64 t2 = __shfl_xor_sync(FULL, gb, o);
            gb = t2 > gb ? t2 : gb;
        }
        if (gb == 0ull) break;                       // prefix set exhausted
        unsigned own = __ballot_sync(FULL, lb == gb);
        int slot = __shfl_sync(FULL, ls, __ffs(own) - 1);
        float4 cand = cbox[slot];
        if (lane == (__ffs(own) - 1)) ckey[slot] = 0ull;
        __syncwarp();
        bool hit = (lane < np) && iou_gt(cand, pick);
        if (__ballot_sync(FULL, hit) == 0u) {
            if (lane == np) pick = cand;
            if (lane == 0) {
                unsigned orig = 0xFFFFFFFFu - (unsigned)gb;
                float* o = out + (b * NUM_PRED + np) * 6;
                o[0] = (float)g_cls[base + orig];
                o[1] = __uint_as_float((unsigned)(gb >> 32));
                o[2] = cand.x; o[3] = cand.y; o[4] = cand.z; o[5] = cand.w;
            }
            np++;
        }
    }

    // exact continuation below the floor (rare: <10 picks / overflow)
    u64 cont = fast ? (((u64)fsb) << 32) : ~0ull;
    while (np < NUM_PRED) {
        u64 lb = 0;
        for (int i = lane; i < NBOX; i += 32) {
            unsigned sb = g_sb[b * NBPAD + i];
            if (!sb) continue;
            u64 k = ((u64)sb << 32) | (u64)(0xFFFFFFFFu - (unsigned)i);
            if (k < cont && k > lb) lb = k;
        }
        u64 gb = lb;
        #pragma unroll
        for (int o = 16; o > 0; o >>= 1) {
            u64 t2 = __shfl_xor_sync(FULL, gb, o);
            gb = t2 > gb ? t2 : gb;
        }
        if (gb == 0ull) break;
        cont = gb;
        unsigned orig = 0xFFFFFFFFu - (unsigned)gb;
        float4 cand = g_box[base + orig];
        bool hit = (lane < np) && iou_gt(cand, pick);
        if (__ballot_sync(FULL, hit) == 0u) {
            if (lane == np) pick = cand;
            if (lane == 0) {
                float* o = out + (b * NUM_PRED + np) * 6;
                o[0] = (float)g_cls[base + orig];
                o[1] = __uint_as_float((unsigned)(gb >> 32));
                o[2] = cand.x; o[3] = cand.y; o[4] = cand.z; o[5] = cand.w;
            }
            np++;
        }
    }
}

extern "C" void kernel_launch(void* const* d_in, const int* in_sizes, int n_in,
                              void* d_out, int out_size) {
    const float* y = (const float*)d_in[0];
    float* out = (float*)d_out;

    dim3 grid(NCHUNK, BATCH);
    fused_kernel<<<grid, DB>>>(y, out);
}

// round 15
// speedup vs baseline: 1.5633x; 1.5633x over previous
#include <cuda_runtime.h>
#include <stdint.h>

#define BATCH 32
#define NBOX 24564
#define NBPAD 24576          // padded to 6144 uint4 per image
#define ROW 93
#define NUM_PRED 10
#define DB 64                // threads per decode CTA
#define NCPB 4               // chunks per decode CTA (double-buffered)
#define NCTA 96              // 384 chunks / 4
#define CHUNK_F4 ((DB * ROW) / 4)   // 1488 float4 per full chunk
#define NBIN 1024
#define CCAP 3072            // smem candidate capacity (24 B/entry = 72 KB)
#define TARGET 128
#define PT 1024              // post_kernel threads

typedef unsigned long long u64;

// Scratch (static device globals; zero-initialized at load).
// g_sb: score bits per box (0 = dead). key = ((u64)sb<<32) | (0xFFFFFFFF-idx).
__device__ unsigned g_sb [BATCH * NBPAD];
__device__ int      g_cls[BATCH * NBOX];
__device__ float4   g_box[BATCH * NBOX];
__device__ int      g_hist[BATCH * NBIN];

// Precise float exp: Cody-Waite + degree-6 FMA poly (~1 ulp), fast-math-proof.
__device__ __forceinline__ float exp_precise(float x) {
    x = fminf(fmaxf(x, -80.0f), 80.0f);
    float kf = rintf(x * 1.4426950408889634f);
    float r  = fmaf(-kf, 0.6931471824645996f, x);
    r        = fmaf(-kf, -1.904654323148236e-09f, r);
    float p  = 1.9875691500e-4f;
    p = fmaf(p, r, 1.3981999507e-3f);
    p = fmaf(p, r, 8.3334519073e-3f);
    p = fmaf(p, r, 4.1665795894e-2f);
    p = fmaf(p, r, 1.6666665459e-1f);
    p = fmaf(p, r, 5.0000000000e-1f);
    p = fmaf(p, r, 1.0f);
    p = fmaf(p, r, 1.0f);
    return p * __int_as_float(((int)kf + 127) << 23);
}

__device__ __forceinline__ void cp16(uint32_t dst_smem, const void* src) {
    asm volatile("cp.async.cg.shared.global [%0], [%1], 16;"
                 :: "r"(dst_smem), "l"(src));
}

// Double-buffered decode: each CTA stages 4 chunks of 64 rows via cp.async,
// overlapping chunk c+1's loads with chunk c's argmax/decode compute.
__global__ __launch_bounds__(DB) void decode_kernel(const float* __restrict__ y) {
    extern __shared__ __align__(16) float sbuf[];     // 2 * CHUNK_F4 float4
    __shared__ int h[NBIN];
    const int b = blockIdx.y;
    const int chunkBase = blockIdx.x * NCPB;          // 0,4,8,...,380
    const int t = threadIdx.x;

    #pragma unroll
    for (int j = 0; j < NBIN / DB; j++) h[t + j * DB] = 0;

    uint32_t sbase;
    asm("{ .reg .u64 tmp; cvta.to.shared.u64 tmp, %1; cvt.u32.u64 %0, tmp; }"
        : "=r"(sbase) : "l"(sbuf));

    // issue chunk 0 load
    {
        const int c0 = chunkBase * DB;
        const int nb = min(DB, NBOX - c0);
        const int nf4 = (nb * ROW) >> 2;
        const float4* src = (const float4*)(y + ((size_t)b * NBOX + c0) * ROW);
        for (int i = t; i < nf4; i += DB) cp16(sbase + i * 16, src + i);
        asm volatile("cp.async.commit_group;" ::: "memory");
    }

    for (int c = 0; c < NCPB; c++) {
        // prefetch chunk c+1 into the other buffer
        if (c + 1 < NCPB) {
            const int c0n = (chunkBase + c + 1) * DB;
            const int nbn = min(DB, NBOX - c0n);
            const int nf4n = (nbn * ROW) >> 2;
            const uint32_t dstb = sbase + ((c + 1) & 1) * (CHUNK_F4 * 16);
            const float4* srcn = (const float4*)(y + ((size_t)b * NBOX + c0n) * ROW);
            for (int i = t; i < nf4n; i += DB) cp16(dstb + i * 16, srcn + i);
            asm volatile("cp.async.commit_group;" ::: "memory");
            asm volatile("cp.async.wait_group 1;" ::: "memory");
        } else {
            asm volatile("cp.async.wait_group 0;" ::: "memory");
        }
        __syncthreads();

        const int c0 = (chunkBase + c) * DB;
        const int nb = min(DB, NBOX - c0);
        const float* s = sbuf + (c & 1) * (CHUNK_F4 * 4);

        if (t < nb) {
            const float* row = s + t * ROW;
            // argmax over 81 classes; '>' keeps first occurrence (jnp.argmax)
            float best = row[0]; int bi = 0;
            #pragma unroll
            for (int cc = 1; cc < 81; cc++) {
                float v = row[cc];
                if (v > best) { best = v; bi = cc; }
            }
            const int box = c0 + t;
            if (bi != 0 && best >= 0.5f) {
                float o0 = row[81], o1 = row[82], o2 = row[83], o3 = row[84];
                float cxp = row[85], cyp = row[86], wp = row[87], hp = row[88];
                float va = row[89], vb = row[90], vc = row[91], vd = row[92];
                float cx = o0 * va * wp + cxp;
                float cy = o1 * vb * hp + cyp;
                float w  = exp_precise(o2 * vc) * wp;
                float hh = exp_precise(o3 * vd) * hp;
                float4 bx;
                bx.x = (cx - 0.5f * w)  * 512.0f;
                bx.y = (cy - 0.5f * hh) * 512.0f;
                bx.z = (cx + 0.5f * w)  * 512.0f;
                bx.w = (cy + 0.5f * hh) * 512.0f;
                unsigned sb = __float_as_uint(best);
                g_sb[b * NBPAD + box] = sb;
                g_cls[b * NBOX + box] = bi;
                g_box[b * NBOX + box] = bx;
                int bin = min(NBIN - 1, (int)((sb - 0x3F000000u) >> 13));
                atomicAdd(&h[bin], 1);
            } else {
                g_sb[b * NBPAD + box] = 0u;
            }
        }
        __syncthreads();   // all reads of this buffer done before it is reloaded
    }

    #pragma unroll
    for (int j = 0; j < NBIN / DB; j++) {
        int i = t + j * DB;
        int c = h[i];
        if (c) atomicAdd(&g_hist[b * NBIN + i], c);
    }
}

__device__ __forceinline__ bool iou_gt(const float4& a, const float4& q) {
    float iw = fminf(a.z, q.z) - fmaxf(a.x, q.x); iw = fmaxf(iw, 0.0f);
    float ih = fminf(a.w, q.w) - fmaxf(a.y, q.y); ih = fmaxf(ih, 0.0f);
    float inter  = iw * ih;
    float area_a = (a.z - a.x) * (a.w - a.y);
    float area_q = (q.z - q.x) * (q.w - q.y);
    return inter / (area_a + area_q - inter + 1e-12f) > 0.35f;
}

// One 1024-thread CTA per image. Floor from 1024-bin hist; uint4 scan of g_sb
// compacts passers (key reconstructed from sb+idx) into smem; warp 0 greedy
// NMS; exact below-floor continuation if <10 picks (rare).  [R13-verified]
__global__ __launch_bounds__(PT) void post_kernel(float* __restrict__ out) {
    extern __shared__ __align__(16) char dsm[];
    float4* s_box = (float4*)dsm;                    // CCAP
    u64*    s_key = (u64*)(s_box + CCAP);            // CCAP
    __shared__ int s_h[NBIN];
    __shared__ int s_c[256];
    __shared__ int s_cnt;
    __shared__ unsigned s_fsb;

    const int b    = blockIdx.x;
    const int tid  = threadIdx.x;
    const int lane = tid & 31;
    const int base = b * NBOX;
    const unsigned FULL = 0xffffffffu;

    if (tid < NUM_PRED * 6) out[b * NUM_PRED * 6 + tid] = 0.0f;
    if (tid == 0) s_cnt = 0;
    if (tid < NBIN) {                                // read + zero hist
        s_h[tid] = g_hist[b * NBIN + tid];
        g_hist[b * NBIN + tid] = 0;
    }
    __syncthreads();
    if (tid < 256)
        s_c[tid] = s_h[tid*4] + s_h[tid*4+1] + s_h[tid*4+2] + s_h[tid*4+3];
    __syncthreads();

    // ---- floor finder (warp 0) ----
    if (tid < 32) {
        int W = 0;
        #pragma unroll
        for (int j = 0; j < 8; j++) W += s_c[lane * 8 + j];
        int suf = W;                                 // suffix sum over lanes
        #pragma unroll
        for (int o = 1; o < 32; o <<= 1) {
            int v = __shfl_down_sync(FULL, suf, o);
            if (lane + o < 32) suf += v;
        }
        int sufnext = __shfl_down_sync(FULL, suf, 1);
        if (lane == 31) sufnext = 0;
        unsigned mask = __ballot_sync(FULL, suf >= TARGET);
        if (mask == 0u) {
            if (lane == 0) s_fsb = 0x3F000000u;      // admit all
        } else {
            int L = 31 - __clz(mask);
            if (lane == L) {
                int cum = sufnext;                   // < TARGET by construction
                int T = 32 * L;
                #pragma unroll
                for (int jb = 31; jb >= 0; jb--) {
                    cum += s_h[32 * L + jb];
                    if (cum >= TARGET) { T = 32 * L + jb; break; }
                }
                s_fsb = 0x3F000000u + ((unsigned)T << 13);
            }
        }
    }
    __syncthreads();
    const unsigned fsb = s_fsb;

    // ---- compact: 6 uint4 loads per thread (whole image, MLP-deep) ----
    {
        const uint4* sb4 = (const uint4*)(g_sb + b * NBPAD);
        uint4 v[6];
        #pragma unroll
        for (int g = 0; g < 6; g++) v[g] = sb4[tid + g * PT];
        #pragma unroll
        for (int g = 0; g < 6; g++) {
            unsigned a0 = v[g].x, a1 = v[g].y, a2 = v[g].z, a3 = v[g].w;
            bool any = (a0 >= fsb) | (a1 >= fsb) | (a2 >= fsb) | (a3 >= fsb);
            if (__ballot_sync(FULL, any) == 0u) continue;   // common case
            #pragma unroll
            for (int c = 0; c < 4; c++) {
                unsigned sb = (c == 0) ? a0 : (c == 1) ? a1 : (c == 2) ? a2 : a3;
                bool pass = (sb >= fsb);
                unsigned m = __ballot_sync(FULL, pass);
                if (m == 0u) continue;
                if (pass) {
                    int leader = __ffs(m) - 1;
                    int wb;
                    if (lane == leader) wb = atomicAdd(&s_cnt, __popc(m));
                    wb = __shfl_sync(m, wb, leader);
                    int slot = wb + __popc(m & ((1u << lane) - 1u));
                    if (slot < CCAP) {
                        int idx = (tid + g * PT) * 4 + c;
                        s_key[slot] = ((u64)sb << 32) |
                                      (u64)(0xFFFFFFFFu - (unsigned)idx);
                        s_box[slot] = g_box[base + idx];
                    }
                }
            }
        }
    }
    __syncthreads();

    // ---- warp 0: greedy NMS over the score-prefix set ----
    if (tid >= 32) return;
    const bool fast = (s_cnt <= CCAP);
    const int M = fast ? s_cnt : 0;
    float4 pick = make_float4(0.f, 0.f, 0.f, 0.f);   // lane i holds pick i
    int np = 0;

    while (np < NUM_PRED) {
        u64 lb = 0; int ls = -1;
        for (int i = lane; i < M; i += 32) {
            u64 k = s_key[i];
            if (k > lb) { lb = k; ls = i; }
        }
        u64 gb = lb;
        #pragma unroll
        for (int o = 16; o > 0; o >>= 1) {
            u64 t2 = __shfl_xor_sync(FULL, gb, o);
            gb = t2 > gb ? t2 : gb;
        }
        if (gb == 0ull) break;                       // prefix set exhausted
        unsigned own = __ballot_sync(FULL, lb == gb);
        int slot = __shfl_sync(FULL, ls, __ffs(own) - 1);
        float4 cand = s_box[slot];
        if (lane == (__ffs(own) - 1)) s_key[slot] = 0ull;
        __syncwarp();
        bool hit = (lane < np) && iou_gt(cand, pick);
        if (__ballot_sync(FULL, hit) == 0u) {
            if (lane == np) pick = cand;
            if (lane == 0) {
                unsigned orig = 0xFFFFFFFFu - (unsigned)gb;
                float* o = out + (b * NUM_PRED + np) * 6;
                o[0] = (float)g_cls[base + orig];
                o[1] = __uint_as_float((unsigned)(gb >> 32));
                o[2] = cand.x; o[3] = cand.y; o[4] = cand.z; o[5] = cand.w;
            }
            np++;
        }
    }

    // exact continuation below the floor (rare: <10 picks survived / overflow)
    u64 cont = fast ? (((u64)fsb) << 32) : ~0ull;
    while (np < NUM_PRED) {
        u64 lb = 0;
        for (int i = lane; i < NBOX; i += 32) {
            unsigned sb = g_sb[b * NBPAD + i];
            if (!sb) continue;
            u64 k = ((u64)sb << 32) | (u64)(0xFFFFFFFFu - (unsigned)i);
            if (k < cont && k > lb) lb = k;
        }
        u64 gb = lb;
        #pragma unroll
        for (int o = 16; o > 0; o >>= 1) {
            u64 t2 = __shfl_xor_sync(FULL, gb, o);
            gb = t2 > gb ? t2 : gb;
        }
        if (gb == 0ull) break;
        cont = gb;
        unsigned orig = 0xFFFFFFFFu - (unsigned)gb;
        float4 cand = g_box[base + orig];
        bool hit = (lane < np) && iou_gt(cand, pick);
        if (__ballot_sync(FULL, hit) == 0u) {
            if (lane == np) pick = cand;
            if (lane == 0) {
                float* o = out + (b * NUM_PRED + np) * 6;
                o[0] = (float)g_cls[base + orig];
                o[1] = __uint_as_float((unsigned)(gb >> 32));
                o[2] = cand.x; o[3] = cand.y; o[4] = cand.z; o[5] = cand.w;
            }
            np++;
        }
    }
}

extern "C" void kernel_launch(void* const* d_in, const int* in_sizes, int n_in,
                              void* d_out, int out_size) {
    const float* y = (const float*)d_in[0];
    float* out = (float*)d_out;

    cudaFuncSetAttribute(decode_kernel, cudaFuncAttributeMaxDynamicSharedMemorySize,
                         2 * CHUNK_F4 * 16);
    cudaFuncSetAttribute(post_kernel, cudaFuncAttributeMaxDynamicSharedMemorySize,
                         CCAP * 24);

    dim3 dgrid(NCTA, BATCH);
    decode_kernel<<<dgrid, DB, 2 * CHUNK_F4 * 16>>>(y);

    post_kernel<<<BATCH, PT, CCAP * 24>>>(out);
}

// round 16
// speedup vs baseline: 1.6462x; 1.0530x over previous
#include <cuda_runtime.h>
#include <stdint.h>

#define BATCH 32
#define NBOX 24564
#define NBPAD 24576          // padded to 6144 uint4 per image
#define ROW 93
#define NUM_PRED 10
#define DB 64                // boxes per decode CTA
#define NBIN 1024
#define CCAP 6144            // smem candidate capacity (24 B/entry = 144 KB)
#define TARGET 64
#define PT 1024              // post_kernel threads

typedef unsigned long long u64;

// Scratch (static device globals; zero-initialized at load).
// g_sb: score bits per box (0 = dead). key = ((u64)sb<<32) | (0xFFFFFFFF-idx).
__device__ unsigned g_sb [BATCH * NBPAD];
__device__ int      g_cls[BATCH * NBOX];
__device__ float4   g_box[BATCH * NBOX];
__device__ int      g_hist[BATCH * NBIN];

// Precise float exp: Cody-Waite + degree-6 FMA poly (~1 ulp), fast-math-proof.
__device__ __forceinline__ float exp_precise(float x) {
    x = fminf(fmaxf(x, -80.0f), 80.0f);
    float kf = rintf(x * 1.4426950408889634f);
    float r  = fmaf(-kf, 0.6931471824645996f, x);
    r        = fmaf(-kf, -1.904654323148236e-09f, r);
    float p  = 1.9875691500e-4f;
    p = fmaf(p, r, 1.3981999507e-3f);
    p = fmaf(p, r, 8.3334519073e-3f);
    p = fmaf(p, r, 4.1665795894e-2f);
    p = fmaf(p, r, 1.6666665459e-1f);
    p = fmaf(p, r, 5.0000000000e-1f);
    p = fmaf(p, r, 1.0f);
    p = fmaf(p, r, 1.0f);
    return p * __int_as_float(((int)kf + 127) << 23);
}

__device__ __forceinline__ void cp16(uint32_t dst_smem, const void* src) {
    asm volatile("cp.async.cg.shared.global [%0], [%1], 16;"
                 :: "r"(dst_smem), "l"(src));
}

// Thread-per-box decode: cp.async staging, per-thread argmax, 1024-bin
// score-bit histogram. [R13-verified]
__global__ __launch_bounds__(DB) void decode_kernel(const float* __restrict__ y) {
    __shared__ float s[DB * ROW];
    __shared__ int   h[NBIN];
    const int b  = blockIdx.y;
    const int c0 = blockIdx.x * DB;
    const int nb = min(DB, NBOX - c0);
    const int nf4 = (nb * ROW) >> 2;
    const int t = threadIdx.x;

    #pragma unroll
    for (int j = 0; j < NBIN / DB; j++) h[t + j * DB] = 0;
    {
        const float4* src = (const float4*)(y + ((size_t)b * NBOX + c0) * ROW);
        uint32_t sbase;
        asm("{ .reg .u64 tmp; cvta.to.shared.u64 tmp, %1; cvt.u32.u64 %0, tmp; }"
            : "=r"(sbase) : "l"(s));
        for (int i = t; i < nf4; i += DB) cp16(sbase + i * 16, src + i);
        asm volatile("cp.async.commit_group;" ::: "memory");
        asm volatile("cp.async.wait_group 0;" ::: "memory");
    }
    __syncthreads();

    if (t < nb) {
        const float* row = s + t * ROW;
        // argmax over 81 classes; '>' keeps first occurrence (jnp.argmax)
        float best = row[0]; int bi = 0;
        #pragma unroll
        for (int c = 1; c < 81; c++) {
            float v = row[c];
            if (v > best) { best = v; bi = c; }
        }
        const int box = c0 + t;
        if (bi != 0 && best >= 0.5f) {
            float o0 = row[81], o1 = row[82], o2 = row[83], o3 = row[84];
            float cxp = row[85], cyp = row[86], wp = row[87], hp = row[88];
            float va = row[89], vb = row[90], vc = row[91], vd = row[92];
            float cx = o0 * va * wp + cxp;
            float cy = o1 * vb * hp + cyp;
            float w  = exp_precise(o2 * vc) * wp;
            float hh = exp_precise(o3 * vd) * hp;
            float4 bx;
            bx.x = (cx - 0.5f * w)  * 512.0f;
            bx.y = (cy - 0.5f * hh) * 512.0f;
            bx.z = (cx + 0.5f * w)  * 512.0f;
            bx.w = (cy + 0.5f * hh) * 512.0f;
            unsigned sb = __float_as_uint(best);
            g_sb[b * NBPAD + box] = sb;
            g_cls[b * NBOX + box] = bi;
            g_box[b * NBOX + box] = bx;
            int bin = min(NBIN - 1, (int)((sb - 0x3F000000u) >> 13));
            atomicAdd(&h[bin], 1);
        } else {
            g_sb[b * NBPAD + box] = 0u;
        }
    }
    __syncthreads();
    #pragma unroll
    for (int j = 0; j < NBIN / DB; j++) {
        int i = t + j * DB;
        int c = h[i];
        if (c) atomicAdd(&g_hist[b * NBIN + i], c);
    }
}

__device__ __forceinline__ bool iou_gt(const float4& a, const float4& q) {
    float iw = fminf(a.z, q.z) - fmaxf(a.x, q.x); iw = fmaxf(iw, 0.0f);
    float ih = fminf(a.w, q.w) - fmaxf(a.y, q.y); ih = fmaxf(ih, 0.0f);
    float inter  = iw * ih;
    float area_a = (a.z - a.x) * (a.w - a.y);
    float area_q = (q.z - q.x) * (q.w - q.y);
    return inter / (area_a + area_q - inter + 1e-12f) > 0.35f;
}

// Warp argmax of 64-bit keys via two 32-bit REDUX stages:
// max score-bits, then min orig-idx among holders. Returns gb (0 if none).
__device__ __forceinline__ u64 warp_key_max(u64 lb, unsigned FULL) {
    unsigned sbmax = __reduce_max_sync(FULL, (unsigned)(lb >> 32));
    if (sbmax == 0u) return 0ull;
    unsigned myidx = ((unsigned)(lb >> 32) == sbmax)
                   ? (0xFFFFFFFFu - (unsigned)lb) : 0xFFFFFFFFu;
    unsigned idxmin = __reduce_min_sync(FULL, myidx);
    return ((u64)sbmax << 32) | (u64)(0xFFFFFFFFu - idxmin);
}

// One 1024-thread CTA per image. Floor from 1024-bin hist; uint4 scan of g_sb
// compacts passers into smem; warp 0 greedy NMS (REDUX argmax); exact
// below-floor continuation if <10 picks (rare).
__global__ __launch_bounds__(PT) void post_kernel(float* __restrict__ out) {
    extern __shared__ __align__(16) char dsm[];
    float4* s_box = (float4*)dsm;                    // CCAP
    u64*    s_key = (u64*)(s_box + CCAP);            // CCAP
    __shared__ int s_h[NBIN];
    __shared__ int s_c[256];
    __shared__ int s_cnt;
    __shared__ unsigned s_fsb;

    const int b    = blockIdx.x;
    const int tid  = threadIdx.x;
    const int lane = tid & 31;
    const int base = b * NBOX;
    const unsigned FULL = 0xffffffffu;

    if (tid < NUM_PRED * 6) out[b * NUM_PRED * 6 + tid] = 0.0f;
    if (tid == 0) s_cnt = 0;
    if (tid < NBIN) {                                // read + zero hist
        s_h[tid] = g_hist[b * NBIN + tid];
        g_hist[b * NBIN + tid] = 0;
    }
    __syncthreads();
    if (tid < 256)
        s_c[tid] = s_h[tid*4] + s_h[tid*4+1] + s_h[tid*4+2] + s_h[tid*4+3];
    __syncthreads();

    // ---- floor finder (warp 0) ----
    if (tid < 32) {
        int W = 0;
        #pragma unroll
        for (int j = 0; j < 8; j++) W += s_c[lane * 8 + j];
        int suf = W;                                 // suffix sum over lanes
        #pragma unroll
        for (int o = 1; o < 32; o <<= 1) {
            int v = __shfl_down_sync(FULL, suf, o);
            if (lane + o < 32) suf += v;
        }
        int sufnext = __shfl_down_sync(FULL, suf, 1);
        if (lane == 31) sufnext = 0;
        unsigned mask = __ballot_sync(FULL, suf >= TARGET);
        if (mask == 0u) {
            if (lane == 0) s_fsb = 0x3F000000u;      // admit all
        } else {
            int L = 31 - __clz(mask);
            if (lane == L) {
                int cum = sufnext;                   // < TARGET by construction
                int T = 32 * L;
                #pragma unroll
                for (int jb = 31; jb >= 0; jb--) {
                    cum += s_h[32 * L + jb];
                    if (cum >= TARGET) { T = 32 * L + jb; break; }
                }
                s_fsb = 0x3F000000u + ((unsigned)T << 13);
            }
        }
    }
    __syncthreads();
    const unsigned fsb = s_fsb;

    // ---- compact: 6 uint4 loads per thread (whole image, MLP-deep) ----
    {
        const uint4* sb4 = (const uint4*)(g_sb + b * NBPAD);
        uint4 v[6];
        #pragma unroll
        for (int g = 0; g < 6; g++) v[g] = sb4[tid + g * PT];
        #pragma unroll
        for (int g = 0; g < 6; g++) {
            unsigned a0 = v[g].x, a1 = v[g].y, a2 = v[g].z, a3 = v[g].w;
            bool any = (a0 >= fsb) | (a1 >= fsb) | (a2 >= fsb) | (a3 >= fsb);
            if (__ballot_sync(FULL, any) == 0u) continue;   // common case
            #pragma unroll
            for (int c = 0; c < 4; c++) {
                unsigned sb = (c == 0) ? a0 : (c == 1) ? a1 : (c == 2) ? a2 : a3;
                bool pass = (sb >= fsb);
                unsigned m = __ballot_sync(FULL, pass);
                if (m == 0u) continue;
                if (pass) {
                    int leader = __ffs(m) - 1;
                    int wb;
                    if (lane == leader) wb = atomicAdd(&s_cnt, __popc(m));
                    wb = __shfl_sync(m, wb, leader);
                    int slot = wb + __popc(m & ((1u << lane) - 1u));
                    if (slot < CCAP) {
                        int idx = (tid + g * PT) * 4 + c;
                        s_key[slot] = ((u64)sb << 32) |
                                      (u64)(0xFFFFFFFFu - (unsigned)idx);
                        s_box[slot] = g_box[base + idx];
                    }
                }
            }
        }
    }
    __syncthreads();

    // ---- warp 0: greedy NMS over the score-prefix set ----
    if (tid >= 32) return;
    const bool fast = (s_cnt <= CCAP);
    const int M = fast ? s_cnt : 0;
    float4 pick = make_float4(0.f, 0.f, 0.f, 0.f);   // lane i holds pick i
    int np = 0;

    while (np < NUM_PRED) {
        u64 lb = 0; int ls = -1;
        for (int i = lane; i < M; i += 32) {
            u64 k = s_key[i];
            if (k > lb) { lb = k; ls = i; }
        }
        u64 gb = warp_key_max(lb, FULL);
        if (gb == 0ull) break;                       // prefix set exhausted
        unsigned own = __ballot_sync(FULL, lb == gb);
        int slot = __shfl_sync(FULL, ls, __ffs(own) - 1);
        float4 cand = s_box[slot];
        if (lane == (__ffs(own) - 1)) s_key[slot] = 0ull;
        __syncwarp();
        bool hit = (lane < np) && iou_gt(cand, pick);
        if (__ballot_sync(FULL, hit) == 0u) {
            if (lane == np) pick = cand;
            if (lane == 0) {
                unsigned orig = 0xFFFFFFFFu - (unsigned)gb;
                float* o = out + (b * NUM_PRED + np) * 6;
                o[0] = (float)g_cls[base + orig];
                o[1] = __uint_as_float((unsigned)(gb >> 32));
                o[2] = cand.x; o[3] = cand.y; o[4] = cand.z; o[5] = cand.w;
            }
            np++;
        }
    }

    // exact continuation below the floor (rare: <10 picks survived / overflow)
    u64 cont = fast ? (((u64)fsb) << 32) : ~0ull;
    while (np < NUM_PRED) {
        u64 lb = 0;
        for (int i = lane; i < NBOX; i += 32) {
            unsigned sb = g_sb[b * NBPAD + i];
            if (!sb) continue;
            u64 k = ((u64)sb << 32) | (u64)(0xFFFFFFFFu - (unsigned)i);
            if (k < cont && k > lb) lb = k;
        }
        u64 gb = warp_key_max(lb, FULL);
        if (gb == 0ull) break;
        cont = gb;
        unsigned orig = 0xFFFFFFFFu - (unsigned)gb;
        float4 cand = g_box[base + orig];
        bool hit = (lane < np) && iou_gt(cand, pick);
        if (__ballot_sync(FULL, hit) == 0u) {
            if (lane == np) pick = cand;
            if (lane == 0) {
                float* o = out + (b * NUM_PRED + np) * 6;
                o[0] = (float)g_cls[base + orig];
                o[1] = __uint_as_float((unsigned)(gb >> 32));
                o[2] = cand.x; o[3] = cand.y; o[4] = cand.z; o[5] = cand.w;
            }
            np++;
        }
    }
}

extern "C" void kernel_launch(void* const* d_in, const int* in_sizes, int n_in,
                              void* d_out, int out_size) {
    const float* y = (const float*)d_in[0];
    float* out = (float*)d_out;

    cudaFuncSetAttribute(post_kernel, cudaFuncAttributeMaxDynamicSharedMemorySize,
                         CCAP * 24);

    dim3 dgrid((NBOX + DB - 1) / DB, BATCH);
    decode_kernel<<<dgrid, DB>>>(y);

    post_kernel<<<BATCH, PT, CCAP * 24>>>(out);
}

// round 17
// speedup vs baseline: 1.6520x; 1.0035x over previous
#include <cuda_runtime.h>
#include <stdint.h>

#define BATCH 32
#define NBOX 24564
#define NBPAD 24576          // padded to 6144 uint4 per image
#define NB4 6144
#define ROW 93
#define NUM_PRED 10
#define DB 64                // boxes per decode CTA
#define NBIN 1024
#define CCAP 4096            // smem candidate capacity
#define TARGET 64
#define PT 1024              // post_kernel threads
// post smem: staging 98304 + cbox CCAP*16 + ckey CCAP*8 = 196608 B
#define POST_SMEM (NB4 * 16 + CCAP * 24)

typedef unsigned long long u64;

// Scratch (static device globals; zero-initialized at load).
// g_sb: score bits per box (0 = dead). key = ((u64)sb<<32) | (0xFFFFFFFF-idx).
__device__ unsigned g_sb [BATCH * NBPAD];
__device__ int      g_cls[BATCH * NBOX];
__device__ float4   g_box[BATCH * NBOX];
__device__ int      g_hist[BATCH * NBIN];

// Precise float exp: Cody-Waite + degree-6 FMA poly (~1 ulp), fast-math-proof.
__device__ __forceinline__ float exp_precise(float x) {
    x = fminf(fmaxf(x, -80.0f), 80.0f);
    float kf = rintf(x * 1.4426950408889634f);
    float r  = fmaf(-kf, 0.6931471824645996f, x);
    r        = fmaf(-kf, -1.904654323148236e-09f, r);
    float p  = 1.9875691500e-4f;
    p = fmaf(p, r, 1.3981999507e-3f);
    p = fmaf(p, r, 8.3334519073e-3f);
    p = fmaf(p, r, 4.1665795894e-2f);
    p = fmaf(p, r, 1.6666665459e-1f);
    p = fmaf(p, r, 5.0000000000e-1f);
    p = fmaf(p, r, 1.0f);
    p = fmaf(p, r, 1.0f);
    return p * __int_as_float(((int)kf + 127) << 23);
}

__device__ __forceinline__ void cp16(uint32_t dst_smem, const void* src) {
    asm volatile("cp.async.cg.shared.global [%0], [%1], 16;"
                 :: "r"(dst_smem), "l"(src));
}

// Thread-per-box decode: cp.async staging, per-thread argmax, 1024-bin
// score-bit histogram. [R13/R16-verified]
__global__ __launch_bounds__(DB) void decode_kernel(const float* __restrict__ y) {
    __shared__ float s[DB * ROW];
    __shared__ int   h[NBIN];
    const int b  = blockIdx.y;
    const int c0 = blockIdx.x * DB;
    const int nb = min(DB, NBOX - c0);
    const int nf4 = (nb * ROW) >> 2;
    const int t = threadIdx.x;

    #pragma unroll
    for (int j = 0; j < NBIN / DB; j++) h[t + j * DB] = 0;
    {
        const float4* src = (const float4*)(y + ((size_t)b * NBOX + c0) * ROW);
        uint32_t sbase;
        asm("{ .reg .u64 tmp; cvta.to.shared.u64 tmp, %1; cvt.u32.u64 %0, tmp; }"
            : "=r"(sbase) : "l"(s));
        for (int i = t; i < nf4; i += DB) cp16(sbase + i * 16, src + i);
        asm volatile("cp.async.commit_group;" ::: "memory");
        asm volatile("cp.async.wait_group 0;" ::: "memory");
    }
    __syncthreads();

    if (t < nb) {
        const float* row = s + t * ROW;
        // argmax over 81 classes; '>' keeps first occurrence (jnp.argmax)
        float best = row[0]; int bi = 0;
        #pragma unroll
        for (int c = 1; c < 81; c++) {
            float v = row[c];
            if (v > best) { best = v; bi = c; }
        }
        const int box = c0 + t;
        if (bi != 0 && best >= 0.5f) {
            float o0 = row[81], o1 = row[82], o2 = row[83], o3 = row[84];
            float cxp = row[85], cyp = row[86], wp = row[87], hp = row[88];
            float va = row[89], vb = row[90], vc = row[91], vd = row[92];
            float cx = o0 * va * wp + cxp;
            float cy = o1 * vb * hp + cyp;
            float w  = exp_precise(o2 * vc) * wp;
            float hh = exp_precise(o3 * vd) * hp;
            float4 bx;
            bx.x = (cx - 0.5f * w)  * 512.0f;
            bx.y = (cy - 0.5f * hh) * 512.0f;
            bx.z = (cx + 0.5f * w)  * 512.0f;
            bx.w = (cy + 0.5f * hh) * 512.0f;
            unsigned sb = __float_as_uint(best);
            g_sb[b * NBPAD + box] = sb;
            g_cls[b * NBOX + box] = bi;
            g_box[b * NBOX + box] = bx;
            int bin = min(NBIN - 1, (int)((sb - 0x3F000000u) >> 13));
            atomicAdd(&h[bin], 1);
        } else {
            g_sb[b * NBPAD + box] = 0u;
        }
    }
    __syncthreads();
    #pragma unroll
    for (int j = 0; j < NBIN / DB; j++) {
        int i = t + j * DB;
        int c = h[i];
        if (c) atomicAdd(&g_hist[b * NBIN + i], c);
    }
}

__device__ __forceinline__ bool iou_gt(const float4& a, const float4& q) {
    float iw = fminf(a.z, q.z) - fmaxf(a.x, q.x); iw = fmaxf(iw, 0.0f);
    float ih = fminf(a.w, q.w) - fmaxf(a.y, q.y); ih = fmaxf(ih, 0.0f);
    float inter  = iw * ih;
    float area_a = (a.z - a.x) * (a.w - a.y);
    float area_q = (q.z - q.x) * (q.w - q.y);
    return inter / (area_a + area_q - inter + 1e-12f) > 0.35f;
}

// Warp argmax of 64-bit keys via two 32-bit REDUX stages.
__device__ __forceinline__ u64 warp_key_max(u64 lb, unsigned FULL) {
    unsigned sbmax = __reduce_max_sync(FULL, (unsigned)(lb >> 32));
    if (sbmax == 0u) return 0ull;
    unsigned myidx = ((unsigned)(lb >> 32) == sbmax)
                   ? (0xFFFFFFFFu - (unsigned)lb) : 0xFFFFFFFFu;
    unsigned idxmin = __reduce_min_sync(FULL, myidx);
    return ((u64)sbmax << 32) | (u64)(0xFFFFFFFFu - idxmin);
}

// One 1024-thread CTA per image. The whole g_sb slice is staged into smem by
// cp.async issued at kernel start (latency overlaps the hist/floor phases);
// compact then runs from smem. Warp 0 greedy NMS (REDUX argmax); exact
// below-floor continuation if <10 picks (rare).
__global__ __launch_bounds__(PT) void post_kernel(float* __restrict__ out) {
    extern __shared__ __align__(16) char dsm[];
    uint4*  s_sb  = (uint4*)dsm;                     // NB4 (98304 B)
    float4* s_box = (float4*)(dsm + NB4 * 16);       // CCAP
    u64*    s_key = (u64*)(dsm + NB4 * 16 + CCAP * 16);  // CCAP
    __shared__ int s_h[NBIN];
    __shared__ int s_c[256];
    __shared__ int s_cnt;
    __shared__ unsigned s_fsb;

    const int b    = blockIdx.x;
    const int tid  = threadIdx.x;
    const int lane = tid & 31;
    const int base = b * NBOX;
    const unsigned FULL = 0xffffffffu;

    // ---- issue the big scan load FIRST (overlaps hist/floor below) ----
    {
        const uint4* sb4 = (const uint4*)(g_sb + b * NBPAD);
        uint32_t sbase;
        asm("{ .reg .u64 tmp; cvta.to.shared.u64 tmp, %1; cvt.u32.u64 %0, tmp; }"
            : "=r"(sbase) : "l"(s_sb));
        #pragma unroll
        for (int g = 0; g < NB4 / PT; g++)
            cp16(sbase + (tid + g * PT) * 16, sb4 + tid + g * PT);
        asm volatile("cp.async.commit_group;" ::: "memory");
    }

    if (tid < NUM_PRED * 6) out[b * NUM_PRED * 6 + tid] = 0.0f;
    if (tid == 0) s_cnt = 0;
    if (tid < NBIN) {                                // read + zero hist
        s_h[tid] = g_hist[b * NBIN + tid];
        g_hist[b * NBIN + tid] = 0;
    }
    __syncthreads();
    if (tid < 256)
        s_c[tid] = s_h[tid*4] + s_h[tid*4+1] + s_h[tid*4+2] + s_h[tid*4+3];
    __syncthreads();

    // ---- floor finder (warp 0) [R11-verified] ----
    if (tid < 32) {
        int W = 0;
        #pragma unroll
        for (int j = 0; j < 8; j++) W += s_c[lane * 8 + j];
        int suf = W;                                 // suffix sum over lanes
        #pragma unroll
        for (int o = 1; o < 32; o <<= 1) {
            int v = __shfl_down_sync(FULL, suf, o);
            if (lane + o < 32) suf += v;
        }
        int sufnext = __shfl_down_sync(FULL, suf, 1);
        if (lane == 31) sufnext = 0;
        unsigned mask = __ballot_sync(FULL, suf >= TARGET);
        if (mask == 0u) {
            if (lane == 0) s_fsb = 0x3F000000u;      // admit all
        } else {
            int L = 31 - __clz(mask);
            if (lane == L) {
                int cum = sufnext;                   // < TARGET by construction
                int T = 32 * L;
                #pragma unroll
                for (int jb = 31; jb >= 0; jb--) {
                    cum += s_h[32 * L + jb];
                    if (cum >= TARGET) { T = 32 * L + jb; break; }
                }
                s_fsb = 0x3F000000u + ((unsigned)T << 13);
            }
        }
    }
    __syncthreads();
    const unsigned fsb = s_fsb;

    // ---- compact from smem staging (each thread reads its own slots) ----
    asm volatile("cp.async.wait_group 0;" ::: "memory");
    {
        #pragma unroll
        for (int g = 0; g < NB4 / PT; g++) {
            uint4 v = s_sb[tid + g * PT];
            unsigned a0 = v.x, a1 = v.y, a2 = v.z, a3 = v.w;
            bool any = (a0 >= fsb) | (a1 >= fsb) | (a2 >= fsb) | (a3 >= fsb);
            if (__ballot_sync(FULL, any) == 0u) continue;   // common case
            #pragma unroll
            for (int c = 0; c < 4; c++) {
                unsigned sb = (c == 0) ? a0 : (c == 1) ? a1 : (c == 2) ? a2 : a3;
                bool pass = (sb >= fsb);
                unsigned m = __ballot_sync(FULL, pass);
                if (m == 0u) continue;
                if (pass) {
                    int leader = __ffs(m) - 1;
                    int wb;
                    if (lane == leader) wb = atomicAdd(&s_cnt, __popc(m));
                    wb = __shfl_sync(m, wb, leader);
                    int slot = wb + __popc(m & ((1u << lane) - 1u));
                    if (slot < CCAP) {
                        int idx = (tid + g * PT) * 4 + c;
                        s_key[slot] = ((u64)sb << 32) |
                                      (u64)(0xFFFFFFFFu - (unsigned)idx);
                        s_box[slot] = g_box[base + idx];
                    }
                }
            }
        }
    }
    __syncthreads();

    // ---- warp 0: greedy NMS over the score-prefix set ----
    if (tid >= 32) return;
    const bool fast = (s_cnt <= CCAP);
    const int M = fast ? s_cnt : 0;
    float4 pick = make_float4(0.f, 0.f, 0.f, 0.f);   // lane i holds pick i
    int np = 0;

    while (np < NUM_PRED) {
        u64 lb = 0; int ls = -1;
        for (int i = lane; i < M; i += 32) {
            u64 k = s_key[i];
            if (k > lb) { lb = k; ls = i; }
        }
        u64 gb = warp_key_max(lb, FULL);
        if (gb == 0ull) break;                       // prefix set exhausted
        unsigned own = __ballot_sync(FULL, lb == gb);
        int slot = __shfl_sync(FULL, ls, __ffs(own) - 1);
        float4 cand = s_box[slot];
        if (lane == (__ffs(own) - 1)) s_key[slot] = 0ull;
        __syncwarp();
        bool hit = (lane < np) && iou_gt(cand, pick);
        if (__ballot_sync(FULL, hit) == 0u) {
            if (lane == np) pick = cand;
            if (lane == 0) {
                unsigned orig = 0xFFFFFFFFu - (unsigned)gb;
                float* o = out + (b * NUM_PRED + np) * 6;
                o[0] = (float)g_cls[base + orig];
                o[1] = __uint_as_float((unsigned)(gb >> 32));
                o[2] = cand.x; o[3] = cand.y; o[4] = cand.z; o[5] = cand.w;
            }
            np++;
        }
    }

    // exact continuation below the floor (rare: <10 picks survived / overflow)
    u64 cont = fast ? (((u64)fsb) << 32) : ~0ull;
    while (np < NUM_PRED) {
        u64 lb = 0;
        for (int i = lane; i < NBOX; i += 32) {
            unsigned sb = g_sb[b * NBPAD + i];
            if (!sb) continue;
            u64 k = ((u64)sb << 32) | (u64)(0xFFFFFFFFu - (unsigned)i);
            if (k < cont && k > lb) lb = k;
        }
        u64 gb = warp_key_max(lb, FULL);
        if (gb == 0ull) break;
        cont = gb;
        unsigned orig = 0xFFFFFFFFu - (unsigned)gb;
        float4 cand = g_box[base + orig];
        bool hit = (lane < np) && iou_gt(cand, pick);
        if (__ballot_sync(FULL, hit) == 0u) {
            if (lane == np) pick = cand;
            if (lane == 0) {
                float* o = out + (b * NUM_PRED + np) * 6;
                o[0] = (float)g_cls[base + orig];
                o[1] = __uint_as_float((unsigned)(gb >> 32));
                o[2] = cand.x; o[3] = cand.y; o[4] = cand.z; o[5] = cand.w;
            }
            np++;
        }
    }
}

extern "C" void kernel_launch(void* const* d_in, const int* in_sizes, int n_in,
                              void* d_out, int out_size) {
    const float* y = (const float*)d_in[0];
    float* out = (float*)d_out;

    cudaFuncSetAttribute(post_kernel, cudaFuncAttributeMaxDynamicSharedMemorySize,
                         POST_SMEM);

    dim3 dgrid((NBOX + DB - 1) / DB, BATCH);
    decode_kernel<<<dgrid, DB>>>(y);

    post_kernel<<<BATCH, PT, POST_SMEM>>>(out);
}